// round 5
// baseline (speedup 1.0000x reference)
#include <cuda_runtime.h>
#include <cuda_bf16.h>
#include <cstdint>

// BahdanauScorer: scores[b,s] = sum_a v_a[a] * tanh( enc[s,b,:].W_s[a,:] + dec[b,:].W_t[a,:] + b_t[a] )
// enc (2048,64,512) f32; dec (64,512); W_s,W_t (512,512); b_t,v_a (512); out (64,2048) f32.
//
// mma.sync (HMMA) bf16 split-3 GEMM: e*w ~= e_hi*w_hi + e_lo*w_hi + e_hi*w_lo,
// double-buffered smem tiles, cp.async for B, one barrier per k-chunk.

#define S_LEN  2048
#define BATCH  64
#define HID    512
#define ATT    512
#define MT     128
#define AC_N   128      // a per chunk
#define KC     64       // k per chunk (floats)
#define NTHR   512

// device scratch
__device__ float         g_dec_att[BATCH * ATT];
__device__ __nv_bfloat16 g_W_hi[ATT * HID];
__device__ __nv_bfloat16 g_W_lo[ATT * HID];

// smem: two buffers of 4 tiles (128x64 bf16 = 16KB each), then dec/v/score
#define TILE_B   16384
#define BUF_B    65536
#define OFF_AHI  0
#define OFF_ALO  16384
#define OFF_BHI  32768
#define OFF_BLO  49152
#define SM_DEC   131072
#define SM_V     133120
#define SM_SCORE 135168
#define SM_TOTAL 135680

__device__ __forceinline__ uint32_t smem_u32(const void* p) {
    uint32_t a;
    asm("{ .reg .u64 t; cvta.to.shared.u64 t, %1; cvt.u32.u64 %0, t; }" : "=r"(a) : "l"(p));
    return a;
}
__device__ __forceinline__ void ldsm4(uint32_t addr, uint32_t* r) {
    asm volatile("ldmatrix.sync.aligned.m8n8.x4.shared.b16 {%0,%1,%2,%3}, [%4];"
                 : "=r"(r[0]), "=r"(r[1]), "=r"(r[2]), "=r"(r[3]) : "r"(addr));
}
__device__ __forceinline__ void cpasync16(uint32_t saddr, const void* gptr) {
    asm volatile("cp.async.cg.shared.global [%0], [%1], 16;" :: "r"(saddr), "l"(gptr) : "memory");
}
#define CP_COMMIT() asm volatile("cp.async.commit_group;" ::: "memory")
#define CP_WAIT0()  asm volatile("cp.async.wait_group 0;" ::: "memory")

#define MMA(d, a, b0, b1)                                                        \
    asm volatile("mma.sync.aligned.m16n8k16.row.col.f32.bf16.bf16.f32 "          \
                 "{%0,%1,%2,%3},{%4,%5,%6,%7},{%8,%9},{%0,%1,%2,%3};"            \
                 : "+f"((d)[0]), "+f"((d)[1]), "+f"((d)[2]), "+f"((d)[3])        \
                 : "r"((a)[0]), "r"((a)[1]), "r"((a)[2]), "r"((a)[3]),           \
                   "r"(b0), "r"(b1))

__device__ __forceinline__ float tanh_fast(float x) {
    float y;
    asm("tanh.approx.f32 %0, %1;" : "=f"(y) : "f"(x));
    return y;
}
__device__ __forceinline__ uint32_t split2(float x0, float x1, uint32_t& lo) {
    __nv_bfloat16 h0 = __float2bfloat16(x0), h1 = __float2bfloat16(x1);
    __nv_bfloat16 l0 = __float2bfloat16(x0 - __bfloat162float(h0));
    __nv_bfloat16 l1 = __float2bfloat16(x1 - __bfloat162float(h1));
    lo = (uint32_t)__bfloat16_as_ushort(l0) | ((uint32_t)__bfloat16_as_ushort(l1) << 16);
    return (uint32_t)__bfloat16_as_ushort(h0) | ((uint32_t)__bfloat16_as_ushort(h1) << 16);
}

// ---------------- merged prep kernel ----------------
// blocks 0..511: W_s -> (hi, lo) bf16 split.  blocks 512..575: dec_att.
__global__ void prep_kernel(const float* __restrict__ W_s,
                            const float* __restrict__ dec_out,
                            const float* __restrict__ W_t,
                            const float* __restrict__ b_t) {
    if (blockIdx.x < 512) {
        int i = blockIdx.x * 512 + threadIdx.x;
        float x = W_s[i];
        __nv_bfloat16 h = __float2bfloat16(x);
        g_W_hi[i] = h;
        g_W_lo[i] = __float2bfloat16(x - __bfloat162float(h));
    } else {
        int b = blockIdx.x - 512;
        __shared__ float dsh[HID];
        for (int i = threadIdx.x; i < HID; i += blockDim.x)
            dsh[i] = dec_out[b * HID + i];
        __syncthreads();
        const float4* dsh4 = reinterpret_cast<const float4*>(dsh);
        for (int a = threadIdx.x; a < ATT; a += blockDim.x) {
            const float4* w4 = reinterpret_cast<const float4*>(W_t + (size_t)a * HID);
            float acc = 0.f;
#pragma unroll 8
            for (int h4 = 0; h4 < HID / 4; ++h4) {
                float4 w = __ldg(&w4[h4]);
                float4 d = dsh4[h4];
                acc += w.x * d.x + w.y * d.y + w.z * d.z + w.w * d.w;
            }
            g_dec_att[b * ATT + a] = acc + b_t[a];
        }
    }
}

// ---------------- main kernel ----------------
extern "C" __global__ void __launch_bounds__(NTHR, 1)
score_mma_kernel(const float* __restrict__ enc,
                 const float* __restrict__ v_a,
                 float* __restrict__ out) {
    extern __shared__ char smem[];
    const uint32_t sb = smem_u32(smem);
    const int tid = threadIdx.x;
    const int lane = tid & 31, wid = tid >> 5;
    const int g = lane >> 2, c = lane & 3, l7 = lane & 7;
    const int t8 = (lane >> 3) & 1, t16 = lane >> 4;
    const int wm = wid & 3, wn = wid >> 2;
    const int mbase = wm * 32, nbase = wn * 32;
    const int b = blockIdx.y, s0 = blockIdx.x * MT;

    float* dec_s = reinterpret_cast<float*>(smem + SM_DEC);
    float* v_s   = reinterpret_cast<float*>(smem + SM_V);
    float* score = reinterpret_cast<float*>(smem + SM_SCORE);
    dec_s[tid] = g_dec_att[b * ATT + tid];
    v_s[tid]   = __ldg(v_a + tid);
    if (tid < MT) score[tid] = 0.f;

    // ldmatrix row bases (within-tile, buffer-independent)
    const int arow = mbase + t8 * 8 + l7;
    const int brow = nbase + t16 * 8 + l7;
    const int axor = arow & 7;
    const int bxor = brow & 7;

    // per-thread fill coordinates (two 16B chunks per tile)
    const int q0 = tid, q1 = tid + NTHR;
    const int ar0 = q0 >> 3, ak0 = q0 & 7;
    const int ar1 = q1 >> 3, ak1 = q1 & 7;
    const uint32_t sw0 = (uint32_t)(ar0 * 128 + ((ak0 ^ (ar0 & 7)) << 4));
    const uint32_t sw1 = (uint32_t)(ar1 * 128 + ((ak1 ^ (ar1 & 7)) << 4));

    const float4* encp0 = reinterpret_cast<const float4*>(
        enc + ((size_t)(s0 + ar0) * BATCH + b) * HID) + ak0 * 2;
    const float4* encp1 = reinterpret_cast<const float4*>(
        enc + ((size_t)(s0 + ar1) * BATCH + b) * HID) + ak1 * 2;

    float4 Araw[4];

    // helper lambdas (inlined by compiler)
    auto ldg_A = [&](int chunk) {
        const int k16 = (chunk & 7) * (KC / 4);   // k offset in float4 units (KC floats = KC/4 float4)
        Araw[0] = __ldg(encp0 + k16);
        Araw[1] = __ldg(encp0 + k16 + 1);
        Araw[2] = __ldg(encp1 + k16);
        Araw[3] = __ldg(encp1 + k16 + 1);
    };
    auto sts_A = [&](int buf) {
        uint4 h, l;
        h.x = split2(Araw[0].x, Araw[0].y, l.x);
        h.y = split2(Araw[0].z, Araw[0].w, l.y);
        h.z = split2(Araw[1].x, Araw[1].y, l.z);
        h.w = split2(Araw[1].z, Araw[1].w, l.w);
        *reinterpret_cast<uint4*>(smem + buf * BUF_B + OFF_AHI + sw0) = h;
        *reinterpret_cast<uint4*>(smem + buf * BUF_B + OFF_ALO + sw0) = l;
        h.x = split2(Araw[2].x, Araw[2].y, l.x);
        h.y = split2(Araw[2].z, Araw[2].w, l.y);
        h.z = split2(Araw[3].x, Araw[3].y, l.z);
        h.w = split2(Araw[3].z, Araw[3].w, l.w);
        *reinterpret_cast<uint4*>(smem + buf * BUF_B + OFF_AHI + sw1) = h;
        *reinterpret_cast<uint4*>(smem + buf * BUF_B + OFF_ALO + sw1) = l;
    };
    auto cp_B = [&](int chunk, int buf) {
        const int a0 = (chunk >> 3) * AC_N, k0 = (chunk & 7) * KC;
        const size_t g0 = (size_t)(a0 + ar0) * HID + k0 + ak0 * 8;
        const size_t g1 = (size_t)(a0 + ar1) * HID + k0 + ak1 * 8;
        const uint32_t bb = sb + buf * BUF_B;
        cpasync16(bb + OFF_BHI + sw0, g_W_hi + g0);
        cpasync16(bb + OFF_BHI + sw1, g_W_hi + g1);
        cpasync16(bb + OFF_BLO + sw0, g_W_lo + g0);
        cpasync16(bb + OFF_BLO + sw1, g_W_lo + g1);
        CP_COMMIT();
    };

    // prologue: chunk 0 into buf 0
    ldg_A(0);
    cp_B(0, 0);
    sts_A(0);
    CP_WAIT0();
    __syncthreads();
    ldg_A(1);          // stage chunk 1 in regs

    float acc[2][4][4];
#pragma unroll
    for (int mi = 0; mi < 2; ++mi)
#pragma unroll
        for (int nj = 0; nj < 4; ++nj)
#pragma unroll
            for (int e = 0; e < 4; ++e) acc[mi][nj][e] = 0.f;

    for (int it = 0; it < 32; ++it) {
        const int cur = it & 1;

        // fill the other buffer with chunk it+1 (A from regs, B via cp.async)
        if (it < 31) {
            sts_A(1 ^ cur);
            cp_B(it + 1, 1 ^ cur);
        }
        // stage chunk it+2 A data into regs (latency hidden under mma)
        if (it < 30) ldg_A(it + 2);

        // ---- mma phase on buf[cur] ----
        const uint32_t bb  = sb + cur * BUF_B;
        const uint32_t uAh = bb + OFF_AHI, uAl = bb + OFF_ALO;
        const uint32_t uBh = bb + OFF_BHI, uBl = bb + OFF_BLO;
#pragma unroll
        for (int ks = 0; ks < 4; ++ks) {
            const int acnk = 2 * ks + t16;
            const int bcnk = 2 * ks + t8;
            uint32_t ah0[4], ah1[4], b0[4], b1[4], t[4];

            ldsm4(uAh + arow * 128 + ((acnk ^ axor) << 4), ah0);
            ldsm4(uAh + (arow + 16) * 128 + ((acnk ^ axor) << 4), ah1);
            ldsm4(uBh + brow * 128 + ((bcnk ^ bxor) << 4), b0);
            ldsm4(uBh + (brow + 16) * 128 + ((bcnk ^ bxor) << 4), b1);

            MMA(acc[0][0], ah0, b0[0], b0[1]);
            MMA(acc[0][1], ah0, b0[2], b0[3]);
            MMA(acc[0][2], ah0, b1[0], b1[1]);
            MMA(acc[0][3], ah0, b1[2], b1[3]);
            MMA(acc[1][0], ah1, b0[0], b0[1]);
            MMA(acc[1][1], ah1, b0[2], b0[3]);
            MMA(acc[1][2], ah1, b1[0], b1[1]);
            MMA(acc[1][3], ah1, b1[2], b1[3]);

            // e_lo * w_hi
            ldsm4(uAl + arow * 128 + ((acnk ^ axor) << 4), t);
            MMA(acc[0][0], t, b0[0], b0[1]);
            MMA(acc[0][1], t, b0[2], b0[3]);
            MMA(acc[0][2], t, b1[0], b1[1]);
            MMA(acc[0][3], t, b1[2], b1[3]);
            ldsm4(uAl + (arow + 16) * 128 + ((acnk ^ axor) << 4), t);
            MMA(acc[1][0], t, b0[0], b0[1]);
            MMA(acc[1][1], t, b0[2], b0[3]);
            MMA(acc[1][2], t, b1[0], b1[1]);
            MMA(acc[1][3], t, b1[2], b1[3]);

            // e_hi * w_lo
            ldsm4(uBl + brow * 128 + ((bcnk ^ bxor) << 4), b0);
            ldsm4(uBl + (brow + 16) * 128 + ((bcnk ^ bxor) << 4), b1);
            MMA(acc[0][0], ah0, b0[0], b0[1]);
            MMA(acc[0][1], ah0, b0[2], b0[3]);
            MMA(acc[0][2], ah0, b1[0], b1[1]);
            MMA(acc[0][3], ah0, b1[2], b1[3]);
            MMA(acc[1][0], ah1, b0[0], b0[1]);
            MMA(acc[1][1], ah1, b0[2], b0[3]);
            MMA(acc[1][2], ah1, b1[0], b1[1]);
            MMA(acc[1][3], ah1, b1[2], b1[3]);
        }

        // end of an a-chunk: tanh + v reduction, reset accumulators
        if ((it & 7) == 7) {
            const int a0 = (it >> 3) * AC_N;
            float pm[4] = {0.f, 0.f, 0.f, 0.f};
#pragma unroll
            for (int mi = 0; mi < 2; ++mi)
#pragma unroll
                for (int nj = 0; nj < 4; ++nj) {
                    const int n = a0 + nbase + nj * 8 + 2 * c;
                    const float dn0 = dec_s[n], dn1 = dec_s[n + 1];
                    const float vn0 = v_s[n],  vn1 = v_s[n + 1];
                    pm[mi * 2 + 0] += vn0 * tanh_fast(acc[mi][nj][0] + dn0)
                                    + vn1 * tanh_fast(acc[mi][nj][1] + dn1);
                    pm[mi * 2 + 1] += vn0 * tanh_fast(acc[mi][nj][2] + dn0)
                                    + vn1 * tanh_fast(acc[mi][nj][3] + dn1);
                }
            atomicAdd(&score[mbase +  0 + g], pm[0]);
            atomicAdd(&score[mbase +  8 + g], pm[1]);
            atomicAdd(&score[mbase + 16 + g], pm[2]);
            atomicAdd(&score[mbase + 24 + g], pm[3]);
#pragma unroll
            for (int mi = 0; mi < 2; ++mi)
#pragma unroll
                for (int nj = 0; nj < 4; ++nj)
#pragma unroll
                    for (int e = 0; e < 4; ++e) acc[mi][nj][e] = 0.f;
        }

        if (it < 31) CP_WAIT0();
        __syncthreads();
    }

    if (tid < MT) out[(size_t)b * S_LEN + s0 + tid] = score[tid];
}

// ---------------- launch ----------------
extern "C" void kernel_launch(void* const* d_in, const int* in_sizes, int n_in,
                              void* d_out, int out_size) {
    const float* dec_out = (const float*)d_in[0];
    const float* enc     = (const float*)d_in[1];
    const float* W_s     = (const float*)d_in[2];
    const float* W_t     = (const float*)d_in[3];
    const float* b_t     = (const float*)d_in[4];
    const float* v_a     = (const float*)d_in[5];
    float* out = (float*)d_out;
    (void)in_sizes; (void)n_in; (void)out_size;

    cudaFuncSetAttribute(score_mma_kernel,
                         cudaFuncAttributeMaxDynamicSharedMemorySize, SM_TOTAL);

    prep_kernel<<<576, 512>>>(W_s, dec_out, W_t, b_t);

    dim3 grid(S_LEN / MT, BATCH);   // (16, 64)
    score_mma_kernel<<<grid, NTHR, SM_TOTAL>>>(enc, v_a, out);
}

// round 6
// speedup vs baseline: 1.1048x; 1.1048x over previous
#include <cuda_runtime.h>
#include <cuda_bf16.h>
#include <cstdint>

// BahdanauScorer: scores[b,s] = sum_a v_a[a] * tanh( enc[s,b,:].W_s[a,:] + dec[b,:].W_t[a,:] + b_t[a] )
// enc (2048,64,512) f32; dec (64,512); W_s,W_t (512,512); b_t,v_a (512); out (64,2048) f32.
//
// mma.sync bf16 split-3 GEMM, double-buffered, cp.async for B.
// MT=64 / 256-thread CTAs so TWO CTAs co-reside per SM (reg+smem fit),
// decorrelating barrier/fill stalls from HMMA issue.

#define S_LEN  2048
#define BATCH  64
#define HID    512
#define ATT    512
#define MT     64       // s-rows per CTA
#define AC_N   128      // a per chunk
#define KC     64       // k per chunk (floats)
#define NTHR   256

// device scratch
__device__ float         g_dec_att[BATCH * ATT];
__device__ __nv_bfloat16 g_W_hi[ATT * HID];
__device__ __nv_bfloat16 g_W_lo[ATT * HID];

// smem: two buffers of {A_hi 8K, A_lo 8K, B_hi 16K, B_lo 16K}, then dec/v/score
#define OFF_AHI  0
#define OFF_ALO  8192
#define OFF_BHI  16384
#define OFF_BLO  32768
#define BUF_B    49152
#define SM_DEC   98304
#define SM_V     100352
#define SM_SCORE 102400
#define SM_TOTAL 102656

__device__ __forceinline__ uint32_t smem_u32(const void* p) {
    uint32_t a;
    asm("{ .reg .u64 t; cvta.to.shared.u64 t, %1; cvt.u32.u64 %0, t; }" : "=r"(a) : "l"(p));
    return a;
}
__device__ __forceinline__ void ldsm4(uint32_t addr, uint32_t* r) {
    asm volatile("ldmatrix.sync.aligned.m8n8.x4.shared.b16 {%0,%1,%2,%3}, [%4];"
                 : "=r"(r[0]), "=r"(r[1]), "=r"(r[2]), "=r"(r[3]) : "r"(addr));
}
__device__ __forceinline__ void cpasync16(uint32_t saddr, const void* gptr) {
    asm volatile("cp.async.cg.shared.global [%0], [%1], 16;" :: "r"(saddr), "l"(gptr) : "memory");
}
#define CP_COMMIT() asm volatile("cp.async.commit_group;" ::: "memory")
#define CP_WAIT0()  asm volatile("cp.async.wait_group 0;" ::: "memory")

#define MMA(d, a, b0, b1)                                                        \
    asm volatile("mma.sync.aligned.m16n8k16.row.col.f32.bf16.bf16.f32 "          \
                 "{%0,%1,%2,%3},{%4,%5,%6,%7},{%8,%9},{%0,%1,%2,%3};"            \
                 : "+f"((d)[0]), "+f"((d)[1]), "+f"((d)[2]), "+f"((d)[3])        \
                 : "r"((a)[0]), "r"((a)[1]), "r"((a)[2]), "r"((a)[3]),           \
                   "r"(b0), "r"(b1))

__device__ __forceinline__ float tanh_fast(float x) {
    float y;
    asm("tanh.approx.f32 %0, %1;" : "=f"(y) : "f"(x));
    return y;
}
__device__ __forceinline__ uint32_t split2(float x0, float x1, uint32_t& lo) {
    __nv_bfloat16 h0 = __float2bfloat16(x0), h1 = __float2bfloat16(x1);
    __nv_bfloat16 l0 = __float2bfloat16(x0 - __bfloat162float(h0));
    __nv_bfloat16 l1 = __float2bfloat16(x1 - __bfloat162float(h1));
    lo = (uint32_t)__bfloat16_as_ushort(l0) | ((uint32_t)__bfloat16_as_ushort(l1) << 16);
    return (uint32_t)__bfloat16_as_ushort(h0) | ((uint32_t)__bfloat16_as_ushort(h1) << 16);
}

// ---------------- merged prep kernel ----------------
__global__ void prep_kernel(const float* __restrict__ W_s,
                            const float* __restrict__ dec_out,
                            const float* __restrict__ W_t,
                            const float* __restrict__ b_t) {
    if (blockIdx.x < 512) {
        int i = blockIdx.x * 512 + threadIdx.x;
        float x = W_s[i];
        __nv_bfloat16 h = __float2bfloat16(x);
        g_W_hi[i] = h;
        g_W_lo[i] = __float2bfloat16(x - __bfloat162float(h));
    } else {
        int b = blockIdx.x - 512;
        __shared__ float dsh[HID];
        for (int i = threadIdx.x; i < HID; i += blockDim.x)
            dsh[i] = dec_out[b * HID + i];
        __syncthreads();
        const float4* dsh4 = reinterpret_cast<const float4*>(dsh);
        for (int a = threadIdx.x; a < ATT; a += blockDim.x) {
            const float4* w4 = reinterpret_cast<const float4*>(W_t + (size_t)a * HID);
            float acc = 0.f;
#pragma unroll 8
            for (int h4 = 0; h4 < HID / 4; ++h4) {
                float4 w = __ldg(&w4[h4]);
                float4 d = dsh4[h4];
                acc += w.x * d.x + w.y * d.y + w.z * d.z + w.w * d.w;
            }
            g_dec_att[b * ATT + a] = acc + b_t[a];
        }
    }
}

// ---------------- main kernel ----------------
extern "C" __global__ void __launch_bounds__(NTHR, 2)
score_mma_kernel(const float* __restrict__ enc,
                 const float* __restrict__ v_a,
                 float* __restrict__ out) {
    extern __shared__ char smem[];
    const uint32_t sb = smem_u32(smem);
    const int tid = threadIdx.x;
    const int lane = tid & 31, wid = tid >> 5;
    const int g = lane >> 2, c = lane & 3, l7 = lane & 7;
    const int t8 = (lane >> 3) & 1, t16 = lane >> 4;
    const int wm = wid & 1, wn = wid >> 1;     // 2 x 4 warp grid
    const int mbase = wm * 32, nbase = wn * 32;
    const int b = blockIdx.y, s0 = blockIdx.x * MT;

    float* dec_s = reinterpret_cast<float*>(smem + SM_DEC);
    float* v_s   = reinterpret_cast<float*>(smem + SM_V);
    float* score = reinterpret_cast<float*>(smem + SM_SCORE);
    dec_s[tid]        = g_dec_att[b * ATT + tid];
    dec_s[tid + 256]  = g_dec_att[b * ATT + tid + 256];
    v_s[tid]          = __ldg(v_a + tid);
    v_s[tid + 256]    = __ldg(v_a + tid + 256);
    if (tid < MT) score[tid] = 0.f;

    // ldmatrix row bases (within-tile)
    const int arow = mbase + t8 * 8 + l7;       // A tile: 64 rows
    const int brow = nbase + t16 * 8 + l7;      // B tile: 128 rows
    const int axor = arow & 7;
    const int bxor = brow & 7;

    // A fill coords: 64 rows x 8 16B-chunks = 512 chunks, 2 per thread
    const int q0 = tid, q1 = tid + NTHR;
    const int ar0 = q0 >> 3, ak0 = q0 & 7;
    const int ar1 = q1 >> 3, ak1 = q1 & 7;
    const uint32_t sw0 = (uint32_t)(ar0 * 128 + ((ak0 ^ (ar0 & 7)) << 4));
    const uint32_t sw1 = (uint32_t)(ar1 * 128 + ((ak1 ^ (ar1 & 7)) << 4));

    // B fill coords: 128 rows x 8 chunks = 1024 chunks, 4 per thread
    int brr[4], bkk[4];
    uint32_t swB[4];
#pragma unroll
    for (int j = 0; j < 4; ++j) {
        const int q = tid + j * NTHR;
        brr[j] = q >> 3; bkk[j] = q & 7;
        swB[j] = (uint32_t)(brr[j] * 128 + ((bkk[j] ^ (brr[j] & 7)) << 4));
    }

    const float4* encp0 = reinterpret_cast<const float4*>(
        enc + ((size_t)(s0 + ar0) * BATCH + b) * HID) + ak0 * 2;
    const float4* encp1 = reinterpret_cast<const float4*>(
        enc + ((size_t)(s0 + ar1) * BATCH + b) * HID) + ak1 * 2;

    float4 Araw[4];

    auto ldg_A = [&](int chunk) {
        const int k16 = (chunk & 7) * (KC / 4);   // float4 units
        Araw[0] = __ldg(encp0 + k16);
        Araw[1] = __ldg(encp0 + k16 + 1);
        Araw[2] = __ldg(encp1 + k16);
        Araw[3] = __ldg(encp1 + k16 + 1);
    };
    auto sts_A = [&](int buf) {
        uint4 h, l;
        h.x = split2(Araw[0].x, Araw[0].y, l.x);
        h.y = split2(Araw[0].z, Araw[0].w, l.y);
        h.z = split2(Araw[1].x, Araw[1].y, l.z);
        h.w = split2(Araw[1].z, Araw[1].w, l.w);
        *reinterpret_cast<uint4*>(smem + buf * BUF_B + OFF_AHI + sw0) = h;
        *reinterpret_cast<uint4*>(smem + buf * BUF_B + OFF_ALO + sw0) = l;
        h.x = split2(Araw[2].x, Araw[2].y, l.x);
        h.y = split2(Araw[2].z, Araw[2].w, l.y);
        h.z = split2(Araw[3].x, Araw[3].y, l.z);
        h.w = split2(Araw[3].z, Araw[3].w, l.w);
        *reinterpret_cast<uint4*>(smem + buf * BUF_B + OFF_AHI + sw1) = h;
        *reinterpret_cast<uint4*>(smem + buf * BUF_B + OFF_ALO + sw1) = l;
    };
    auto cp_B = [&](int chunk, int buf) {
        const int a0 = (chunk >> 3) * AC_N, k0 = (chunk & 7) * KC;
        const uint32_t bb = sb + buf * BUF_B;
#pragma unroll
        for (int j = 0; j < 4; ++j) {
            const size_t gg = (size_t)(a0 + brr[j]) * HID + k0 + bkk[j] * 8;
            cpasync16(bb + OFF_BHI + swB[j], g_W_hi + gg);
            cpasync16(bb + OFF_BLO + swB[j], g_W_lo + gg);
        }
        CP_COMMIT();
    };

    // prologue: chunk 0 into buf 0
    ldg_A(0);
    cp_B(0, 0);
    sts_A(0);
    CP_WAIT0();
    __syncthreads();
    ldg_A(1);

    float acc[2][4][4];
#pragma unroll
    for (int mi = 0; mi < 2; ++mi)
#pragma unroll
        for (int nj = 0; nj < 4; ++nj)
#pragma unroll
            for (int e = 0; e < 4; ++e) acc[mi][nj][e] = 0.f;

    for (int it = 0; it < 32; ++it) {
        const int cur = it & 1;

        if (it < 31) {
            sts_A(1 ^ cur);
            cp_B(it + 1, 1 ^ cur);
        }
        if (it < 30) ldg_A(it + 2);

        // ---- mma phase on buf[cur] ----
        const uint32_t bb  = sb + cur * BUF_B;
        const uint32_t uAh = bb + OFF_AHI, uAl = bb + OFF_ALO;
        const uint32_t uBh = bb + OFF_BHI, uBl = bb + OFF_BLO;
#pragma unroll
        for (int ks = 0; ks < 4; ++ks) {
            const int acnk = 2 * ks + t16;
            const int bcnk = 2 * ks + t8;
            uint32_t ah0[4], ah1[4], b0[4], b1[4], t[4];

            ldsm4(uAh + arow * 128 + ((acnk ^ axor) << 4), ah0);
            ldsm4(uAh + (arow + 16) * 128 + ((acnk ^ axor) << 4), ah1);
            ldsm4(uBh + brow * 128 + ((bcnk ^ bxor) << 4), b0);
            ldsm4(uBh + (brow + 16) * 128 + ((bcnk ^ bxor) << 4), b1);

            MMA(acc[0][0], ah0, b0[0], b0[1]);
            MMA(acc[0][1], ah0, b0[2], b0[3]);
            MMA(acc[0][2], ah0, b1[0], b1[1]);
            MMA(acc[0][3], ah0, b1[2], b1[3]);
            MMA(acc[1][0], ah1, b0[0], b0[1]);
            MMA(acc[1][1], ah1, b0[2], b0[3]);
            MMA(acc[1][2], ah1, b1[0], b1[1]);
            MMA(acc[1][3], ah1, b1[2], b1[3]);

            // e_lo * w_hi
            ldsm4(uAl + arow * 128 + ((acnk ^ axor) << 4), t);
            MMA(acc[0][0], t, b0[0], b0[1]);
            MMA(acc[0][1], t, b0[2], b0[3]);
            MMA(acc[0][2], t, b1[0], b1[1]);
            MMA(acc[0][3], t, b1[2], b1[3]);
            ldsm4(uAl + (arow + 16) * 128 + ((acnk ^ axor) << 4), t);
            MMA(acc[1][0], t, b0[0], b0[1]);
            MMA(acc[1][1], t, b0[2], b0[3]);
            MMA(acc[1][2], t, b1[0], b1[1]);
            MMA(acc[1][3], t, b1[2], b1[3]);

            // e_hi * w_lo
            ldsm4(uBl + brow * 128 + ((bcnk ^ bxor) << 4), b0);
            ldsm4(uBl + (brow + 16) * 128 + ((bcnk ^ bxor) << 4), b1);
            MMA(acc[0][0], ah0, b0[0], b0[1]);
            MMA(acc[0][1], ah0, b0[2], b0[3]);
            MMA(acc[0][2], ah0, b1[0], b1[1]);
            MMA(acc[0][3], ah0, b1[2], b1[3]);
            MMA(acc[1][0], ah1, b0[0], b0[1]);
            MMA(acc[1][1], ah1, b0[2], b0[3]);
            MMA(acc[1][2], ah1, b1[0], b1[1]);
            MMA(acc[1][3], ah1, b1[2], b1[3]);
        }

        // end of an a-chunk: tanh + v reduction, reset accumulators
        if ((it & 7) == 7) {
            const int a0 = (it >> 3) * AC_N;
            float pm[4] = {0.f, 0.f, 0.f, 0.f};
#pragma unroll
            for (int mi = 0; mi < 2; ++mi)
#pragma unroll
                for (int nj = 0; nj < 4; ++nj) {
                    const int n = a0 + nbase + nj * 8 + 2 * c;
                    const float dn0 = dec_s[n], dn1 = dec_s[n + 1];
                    const float vn0 = v_s[n],  vn1 = v_s[n + 1];
                    pm[mi * 2 + 0] += vn0 * tanh_fast(acc[mi][nj][0] + dn0)
                                    + vn1 * tanh_fast(acc[mi][nj][1] + dn1);
                    pm[mi * 2 + 1] += vn0 * tanh_fast(acc[mi][nj][2] + dn0)
                                    + vn1 * tanh_fast(acc[mi][nj][3] + dn1);
                }
            atomicAdd(&score[mbase +  0 + g], pm[0]);
            atomicAdd(&score[mbase +  8 + g], pm[1]);
            atomicAdd(&score[mbase + 16 + g], pm[2]);
            atomicAdd(&score[mbase + 24 + g], pm[3]);
#pragma unroll
            for (int mi = 0; mi < 2; ++mi)
#pragma unroll
                for (int nj = 0; nj < 4; ++nj)
#pragma unroll
                    for (int e = 0; e < 4; ++e) acc[mi][nj][e] = 0.f;
        }

        if (it < 31) CP_WAIT0();
        __syncthreads();
    }

    if (tid < MT) out[(size_t)b * S_LEN + s0 + tid] = score[tid];
}

// ---------------- launch ----------------
extern "C" void kernel_launch(void* const* d_in, const int* in_sizes, int n_in,
                              void* d_out, int out_size) {
    const float* dec_out = (const float*)d_in[0];
    const float* enc     = (const float*)d_in[1];
    const float* W_s     = (const float*)d_in[2];
    const float* W_t     = (const float*)d_in[3];
    const float* b_t     = (const float*)d_in[4];
    const float* v_a     = (const float*)d_in[5];
    float* out = (float*)d_out;
    (void)in_sizes; (void)n_in; (void)out_size;

    cudaFuncSetAttribute(score_mma_kernel,
                         cudaFuncAttributeMaxDynamicSharedMemorySize, SM_TOTAL);

    prep_kernel<<<576, 512>>>(W_s, dec_out, W_t, b_t);

    dim3 grid(S_LEN / MT, BATCH);   // (32, 64) = 2048 CTAs
    score_mma_kernel<<<grid, NTHR, SM_TOTAL>>>(enc, v_a, out);
}

// round 9
// speedup vs baseline: 1.4017x; 1.2687x over previous
#include <cuda_runtime.h>
#include <cuda_fp16.h>
#include <cstdint>

// BahdanauScorer: scores[b,s] = sum_a v_a[a] * tanh( enc[s,b,:].W_s[a,:] + dec[b,:].W_t[a,:] + b_t[a] )
// enc (2048,64,512) f32; dec (64,512); W_s,W_t (512,512); b_t,v_a (512); out (64,2048) f32.
//
// mma.sync fp16 split-2 GEMM: e*w ~= e_hi*w + e_lo*w  (w single fp16; e split to ~2^-22).
// Double-buffered smem, cp.async for W, 2 CTAs/SM.

#define S_LEN  2048
#define BATCH  64
#define HID    512
#define ATT    512
#define MT     64       // s-rows per CTA
#define AC_N   128      // a per chunk
#define KC     64       // k per chunk (floats)
#define NTHR   256

// device scratch
__device__ float  g_dec_att[BATCH * ATT];
__device__ __half g_W_h[ATT * HID];

// smem: two buffers of {A_hi 8K, A_lo 8K, B 16K}, then dec/v/score
#define OFF_AHI  0
#define OFF_ALO  8192
#define OFF_B    16384
#define BUF_B    32768
#define SM_DEC   65536
#define SM_V     67584
#define SM_SCORE 69632
#define SM_TOTAL 69888

__device__ __forceinline__ uint32_t smem_u32(const void* p) {
    uint32_t a;
    asm("{ .reg .u64 t; cvta.to.shared.u64 t, %1; cvt.u32.u64 %0, t; }" : "=r"(a) : "l"(p));
    return a;
}
__device__ __forceinline__ void ldsm4(uint32_t addr, uint32_t* r) {
    asm volatile("ldmatrix.sync.aligned.m8n8.x4.shared.b16 {%0,%1,%2,%3}, [%4];"
                 : "=r"(r[0]), "=r"(r[1]), "=r"(r[2]), "=r"(r[3]) : "r"(addr));
}
__device__ __forceinline__ void cpasync16(uint32_t saddr, const void* gptr) {
    asm volatile("cp.async.cg.shared.global [%0], [%1], 16;" :: "r"(saddr), "l"(gptr) : "memory");
}
#define CP_COMMIT() asm volatile("cp.async.commit_group;" ::: "memory")
#define CP_WAIT0()  asm volatile("cp.async.wait_group 0;" ::: "memory")

#define MMA(d, a, b0, b1)                                                        \
    asm volatile("mma.sync.aligned.m16n8k16.row.col.f32.f16.f16.f32 "            \
                 "{%0,%1,%2,%3},{%4,%5,%6,%7},{%8,%9},{%0,%1,%2,%3};"            \
                 : "+f"((d)[0]), "+f"((d)[1]), "+f"((d)[2]), "+f"((d)[3])        \
                 : "r"((a)[0]), "r"((a)[1]), "r"((a)[2]), "r"((a)[3]),           \
                   "r"(b0), "r"(b1))

__device__ __forceinline__ float tanh_fast(float x) {
    float y;
    asm("tanh.approx.f32 %0, %1;" : "=f"(y) : "f"(x));
    return y;
}
// pack two floats into fp16x2 hi parts, residual into lo
__device__ __forceinline__ uint32_t split2h(float x0, float x1, uint32_t& lo) {
    __half h0 = __float2half_rn(x0), h1 = __float2half_rn(x1);
    __half l0 = __float2half_rn(x0 - __half2float(h0));
    __half l1 = __float2half_rn(x1 - __half2float(h1));
    lo = (uint32_t)__half_as_ushort(l0) | ((uint32_t)__half_as_ushort(l1) << 16);
    return (uint32_t)__half_as_ushort(h0) | ((uint32_t)__half_as_ushort(h1) << 16);
}

// ---------------- merged prep kernel ----------------
// blocks 0..511: W_s -> fp16.  blocks 512..575: dec_att.
__global__ void prep_kernel(const float* __restrict__ W_s,
                            const float* __restrict__ dec_out,
                            const float* __restrict__ W_t,
                            const float* __restrict__ b_t) {
    if (blockIdx.x < 512) {
        int i = blockIdx.x * 512 + threadIdx.x;
        g_W_h[i] = __float2half_rn(W_s[i]);
    } else {
        int b = blockIdx.x - 512;
        __shared__ float dsh[HID];
        for (int i = threadIdx.x; i < HID; i += blockDim.x)
            dsh[i] = dec_out[b * HID + i];
        __syncthreads();
        const float4* dsh4 = reinterpret_cast<const float4*>(dsh);
        for (int a = threadIdx.x; a < ATT; a += blockDim.x) {
            const float4* w4 = reinterpret_cast<const float4*>(W_t + (size_t)a * HID);
            float acc = 0.f;
#pragma unroll 8
            for (int h4 = 0; h4 < HID / 4; ++h4) {
                float4 w = __ldg(&w4[h4]);
                float4 d = dsh4[h4];
                acc += w.x * d.x + w.y * d.y + w.z * d.z + w.w * d.w;
            }
            g_dec_att[b * ATT + a] = acc + b_t[a];
        }
    }
}

// ---------------- main kernel ----------------
extern "C" __global__ void __launch_bounds__(NTHR, 2)
score_mma_kernel(const float* __restrict__ enc,
                 const float* __restrict__ v_a,
                 float* __restrict__ out) {
    extern __shared__ char smem[];
    const uint32_t sb = smem_u32(smem);
    const int tid = threadIdx.x;
    const int lane = tid & 31, wid = tid >> 5;
    const int g = lane >> 2, c = lane & 3, l7 = lane & 7;
    const int t8 = (lane >> 3) & 1, t16 = lane >> 4;
    const int wm = wid & 1, wn = wid >> 1;     // 2 x 4 warp grid
    const int mbase = wm * 32, nbase = wn * 32;
    const int b = blockIdx.y, s0 = blockIdx.x * MT;

    float* dec_s = reinterpret_cast<float*>(smem + SM_DEC);
    float* v_s   = reinterpret_cast<float*>(smem + SM_V);
    float* score = reinterpret_cast<float*>(smem + SM_SCORE);
    dec_s[tid]        = g_dec_att[b * ATT + tid];
    dec_s[tid + 256]  = g_dec_att[b * ATT + tid + 256];
    v_s[tid]          = __ldg(v_a + tid);
    v_s[tid + 256]    = __ldg(v_a + tid + 256);
    if (tid < MT) score[tid] = 0.f;

    // ldmatrix row bases
    const int arow = mbase + t8 * 8 + l7;       // A tile: 64 rows
    const int brow = nbase + t16 * 8 + l7;      // B tile: 128 rows
    const int axor = arow & 7;
    const int bxor = brow & 7;

    // A fill coords: 64 rows x 8 16B-chunks = 512 chunks, 2 per thread
    const int q0 = tid, q1 = tid + NTHR;
    const int ar0 = q0 >> 3, ak0 = q0 & 7;
    const int ar1 = q1 >> 3, ak1 = q1 & 7;
    const uint32_t sw0 = (uint32_t)(ar0 * 128 + ((ak0 ^ (ar0 & 7)) << 4));
    const uint32_t sw1 = (uint32_t)(ar1 * 128 + ((ak1 ^ (ar1 & 7)) << 4));

    // B fill coords: 128 rows x 8 chunks = 1024 chunks, 4 per thread
    int brr[4], bkk[4];
    uint32_t swB[4];
#pragma unroll
    for (int j = 0; j < 4; ++j) {
        const int q = tid + j * NTHR;
        brr[j] = q >> 3; bkk[j] = q & 7;
        swB[j] = (uint32_t)(brr[j] * 128 + ((bkk[j] ^ (brr[j] & 7)) << 4));
    }

    const float4* encp0 = reinterpret_cast<const float4*>(
        enc + ((size_t)(s0 + ar0) * BATCH + b) * HID) + ak0 * 2;
    const float4* encp1 = reinterpret_cast<const float4*>(
        enc + ((size_t)(s0 + ar1) * BATCH + b) * HID) + ak1 * 2;

    float4 Araw[4];

    auto ldg_A = [&](int chunk) {
        const int k16 = (chunk & 7) * (KC / 4);   // float4 units
        Araw[0] = __ldg(encp0 + k16);
        Araw[1] = __ldg(encp0 + k16 + 1);
        Araw[2] = __ldg(encp1 + k16);
        Araw[3] = __ldg(encp1 + k16 + 1);
    };
    auto sts_A = [&](int buf) {
        uint4 h, l;
        h.x = split2h(Araw[0].x, Araw[0].y, l.x);
        h.y = split2h(Araw[0].z, Araw[0].w, l.y);
        h.z = split2h(Araw[1].x, Araw[1].y, l.z);
        h.w = split2h(Araw[1].z, Araw[1].w, l.w);
        *reinterpret_cast<uint4*>(smem + buf * BUF_B + OFF_AHI + sw0) = h;
        *reinterpret_cast<uint4*>(smem + buf * BUF_B + OFF_ALO + sw0) = l;
        h.x = split2h(Araw[2].x, Araw[2].y, l.x);
        h.y = split2h(Araw[2].z, Araw[2].w, l.y);
        h.z = split2h(Araw[3].x, Araw[3].y, l.z);
        h.w = split2h(Araw[3].z, Araw[3].w, l.w);
        *reinterpret_cast<uint4*>(smem + buf * BUF_B + OFF_AHI + sw1) = h;
        *reinterpret_cast<uint4*>(smem + buf * BUF_B + OFF_ALO + sw1) = l;
    };
    auto cp_B = [&](int chunk, int buf) {
        const int a0 = (chunk >> 3) * AC_N, k0 = (chunk & 7) * KC;
        const uint32_t bb = sb + buf * BUF_B;
#pragma unroll
        for (int j = 0; j < 4; ++j) {
            const size_t gg = (size_t)(a0 + brr[j]) * HID + k0 + bkk[j] * 8;
            cpasync16(bb + OFF_B + swB[j], g_W_h + gg);
        }
        CP_COMMIT();
    };

    // prologue: chunk 0 into buf 0
    ldg_A(0);
    cp_B(0, 0);
    sts_A(0);
    CP_WAIT0();
    __syncthreads();
    ldg_A(1);

    float acc[2][4][4];
#pragma unroll
    for (int mi = 0; mi < 2; ++mi)
#pragma unroll
        for (int nj = 0; nj < 4; ++nj)
#pragma unroll
            for (int e = 0; e < 4; ++e) acc[mi][nj][e] = 0.f;

    for (int it = 0; it < 32; ++it) {
        const int cur = it & 1;

        if (it < 31) {
            sts_A(1 ^ cur);
            cp_B(it + 1, 1 ^ cur);
        }
        if (it < 30) ldg_A(it + 2);

        // ---- mma phase on buf[cur] ----
        const uint32_t bb  = sb + cur * BUF_B;
        const uint32_t uAh = bb + OFF_AHI, uAl = bb + OFF_ALO;
        const uint32_t uB  = bb + OFF_B;
#pragma unroll
        for (int ks = 0; ks < 4; ++ks) {
            const int acnk = 2 * ks + t16;
            const int bcnk = 2 * ks + t8;
            uint32_t ah0[4], ah1[4], al0[4], al1[4], b0[4], b1[4];

            ldsm4(uB + brow * 128 + ((bcnk ^ bxor) << 4), b0);
            ldsm4(uB + (brow + 16) * 128 + ((bcnk ^ bxor) << 4), b1);
            ldsm4(uAh + arow * 128 + ((acnk ^ axor) << 4), ah0);
            ldsm4(uAh + (arow + 16) * 128 + ((acnk ^ axor) << 4), ah1);
            ldsm4(uAl + arow * 128 + ((acnk ^ axor) << 4), al0);
            ldsm4(uAl + (arow + 16) * 128 + ((acnk ^ axor) << 4), al1);

            // e_hi * w
            MMA(acc[0][0], ah0, b0[0], b0[1]);
            MMA(acc[0][1], ah0, b0[2], b0[3]);
            MMA(acc[0][2], ah0, b1[0], b1[1]);
            MMA(acc[0][3], ah0, b1[2], b1[3]);
            MMA(acc[1][0], ah1, b0[0], b0[1]);
            MMA(acc[1][1], ah1, b0[2], b0[3]);
            MMA(acc[1][2], ah1, b1[0], b1[1]);
            MMA(acc[1][3], ah1, b1[2], b1[3]);
            // e_lo * w
            MMA(acc[0][0], al0, b0[0], b0[1]);
            MMA(acc[0][1], al0, b0[2], b0[3]);
            MMA(acc[0][2], al0, b1[0], b1[1]);
            MMA(acc[0][3], al0, b1[2], b1[3]);
            MMA(acc[1][0], al1, b0[0], b0[1]);
            MMA(acc[1][1], al1, b0[2], b0[3]);
            MMA(acc[1][2], al1, b1[0], b1[1]);
            MMA(acc[1][3], al1, b1[2], b1[3]);
        }

        // end of an a-chunk: tanh + v reduction, reset accumulators
        if ((it & 7) == 7) {
            const int a0 = (it >> 3) * AC_N;
            float pm[4] = {0.f, 0.f, 0.f, 0.f};
#pragma unroll
            for (int mi = 0; mi < 2; ++mi)
#pragma unroll
                for (int nj = 0; nj < 4; ++nj) {
                    const int n = a0 + nbase + nj * 8 + 2 * c;
                    const float dn0 = dec_s[n], dn1 = dec_s[n + 1];
                    const float vn0 = v_s[n],  vn1 = v_s[n + 1];
                    pm[mi * 2 + 0] += vn0 * tanh_fast(acc[mi][nj][0] + dn0)
                                    + vn1 * tanh_fast(acc[mi][nj][1] + dn1);
                    pm[mi * 2 + 1] += vn0 * tanh_fast(acc[mi][nj][2] + dn0)
                                    + vn1 * tanh_fast(acc[mi][nj][3] + dn1);
                }
            atomicAdd(&score[mbase +  0 + g], pm[0]);
            atomicAdd(&score[mbase +  8 + g], pm[1]);
            atomicAdd(&score[mbase + 16 + g], pm[2]);
            atomicAdd(&score[mbase + 24 + g], pm[3]);
#pragma unroll
            for (int mi = 0; mi < 2; ++mi)
#pragma unroll
                for (int nj = 0; nj < 4; ++nj)
#pragma unroll
                    for (int e = 0; e < 4; ++e) acc[mi][nj][e] = 0.f;
        }

        if (it < 31) CP_WAIT0();
        __syncthreads();
    }

    if (tid < MT) out[(size_t)b * S_LEN + s0 + tid] = score[tid];
}

// ---------------- launch ----------------
extern "C" void kernel_launch(void* const* d_in, const int* in_sizes, int n_in,
                              void* d_out, int out_size) {
    const float* dec_out = (const float*)d_in[0];
    const float* enc     = (const float*)d_in[1];
    const float* W_s     = (const float*)d_in[2];
    const float* W_t     = (const float*)d_in[3];
    const float* b_t     = (const float*)d_in[4];
    const float* v_a     = (const float*)d_in[5];
    float* out = (float*)d_out;
    (void)in_sizes; (void)n_in; (void)out_size;

    cudaFuncSetAttribute(score_mma_kernel,
                         cudaFuncAttributeMaxDynamicSharedMemorySize, SM_TOTAL);

    prep_kernel<<<576, 512>>>(W_s, dec_out, W_t, b_t);

    dim3 grid(S_LEN / MT, BATCH);   // (32, 64) = 2048 CTAs
    score_mma_kernel<<<grid, NTHR, SM_TOTAL>>>(enc, v_a, out);
}

// round 10
// speedup vs baseline: 2.0109x; 1.4346x over previous
#include <cuda_runtime.h>
#include <cuda_fp16.h>
#include <cstdint>

// BahdanauScorer: scores[b,s] = sum_a v_a[a] * tanh( enc[s,b,:].W_s[a,:] + dec[b,:].W_t[a,:] + b_t[a] )
// enc (2048,64,512) f32; dec (64,512); W_s,W_t (512,512); b_t,v_a (512); out (64,2048) f32.
//
// mma.sync fp16 x fp16 (single pass). Error budget: w-rounding (measured 1.69e-4 rel)
// + e-rounding (same magnitude, independent) => ~2.4e-4 rel, 4x under 1e-3 threshold.
// Double-buffered smem, cp.async for W, 2 CTAs/SM.

#define S_LEN  2048
#define BATCH  64
#define HID    512
#define ATT    512
#define MT     64       // s-rows per CTA
#define AC_N   128      // a per chunk
#define KC     64       // k per chunk (floats)
#define NTHR   256

// device scratch
__device__ float  g_dec_att[BATCH * ATT];
__device__ __half g_W_h[ATT * HID];

// smem: two buffers of {A 8K, B 16K}, then dec/v/score
#define OFF_A    0
#define OFF_B    8192
#define BUF_B    24576
#define SM_DEC   49152
#define SM_V     51200
#define SM_SCORE 53248
#define SM_TOTAL 53504

__device__ __forceinline__ uint32_t smem_u32(const void* p) {
    uint32_t a;
    asm("{ .reg .u64 t; cvta.to.shared.u64 t, %1; cvt.u32.u64 %0, t; }" : "=r"(a) : "l"(p));
    return a;
}
__device__ __forceinline__ void ldsm4(uint32_t addr, uint32_t* r) {
    asm volatile("ldmatrix.sync.aligned.m8n8.x4.shared.b16 {%0,%1,%2,%3}, [%4];"
                 : "=r"(r[0]), "=r"(r[1]), "=r"(r[2]), "=r"(r[3]) : "r"(addr));
}
__device__ __forceinline__ void cpasync16(uint32_t saddr, const void* gptr) {
    asm volatile("cp.async.cg.shared.global [%0], [%1], 16;" :: "r"(saddr), "l"(gptr) : "memory");
}
#define CP_COMMIT() asm volatile("cp.async.commit_group;" ::: "memory")
#define CP_WAIT0()  asm volatile("cp.async.wait_group 0;" ::: "memory")

#define MMA(d, a, b0, b1)                                                        \
    asm volatile("mma.sync.aligned.m16n8k16.row.col.f32.f16.f16.f32 "            \
                 "{%0,%1,%2,%3},{%4,%5,%6,%7},{%8,%9},{%0,%1,%2,%3};"            \
                 : "+f"((d)[0]), "+f"((d)[1]), "+f"((d)[2]), "+f"((d)[3])        \
                 : "r"((a)[0]), "r"((a)[1]), "r"((a)[2]), "r"((a)[3]),           \
                   "r"(b0), "r"(b1))

__device__ __forceinline__ float tanh_fast(float x) {
    float y;
    asm("tanh.approx.f32 %0, %1;" : "=f"(y) : "f"(x));
    return y;
}
__device__ __forceinline__ uint32_t cvt2h(float x0, float x1) {
    __half2 h = __floats2half2_rn(x0, x1);
    return *reinterpret_cast<uint32_t*>(&h);
}

// ---------------- merged prep kernel ----------------
// blocks 0..511: W_s -> fp16.  blocks 512..767: dec_att (4 blocks per batch).
__global__ void prep_kernel(const float* __restrict__ W_s,
                            const float* __restrict__ dec_out,
                            const float* __restrict__ W_t,
                            const float* __restrict__ b_t) {
    if (blockIdx.x < 512) {
        int i = blockIdx.x * 512 + threadIdx.x;
        g_W_h[i] = __float2half_rn(W_s[i]);
    } else {
        const int bq = blockIdx.x - 512;
        const int b = bq >> 2, aq = bq & 3;
        __shared__ float dsh[HID];
        for (int i = threadIdx.x; i < HID; i += blockDim.x)
            dsh[i] = dec_out[b * HID + i];
        __syncthreads();
        // 512 threads = 128 a-rows x 4 h-quarters
        const int a = aq * 128 + (threadIdx.x >> 2);
        const int part = threadIdx.x & 3;
        const float4* w4 = reinterpret_cast<const float4*>(W_t + (size_t)a * HID) + part * 32;
        const float4* d4 = reinterpret_cast<const float4*>(dsh) + part * 32;
        float acc = 0.f;
#pragma unroll 8
        for (int h4 = 0; h4 < 32; ++h4) {
            float4 w = __ldg(&w4[h4]);
            float4 d = d4[h4];
            acc += w.x * d.x + w.y * d.y + w.z * d.z + w.w * d.w;
        }
        acc += __shfl_down_sync(0xffffffffu, acc, 1);
        acc += __shfl_down_sync(0xffffffffu, acc, 2);
        if (part == 0) g_dec_att[b * ATT + a] = acc + b_t[a];
    }
}

// ---------------- main kernel ----------------
extern "C" __global__ void __launch_bounds__(NTHR, 2)
score_mma_kernel(const float* __restrict__ enc,
                 const float* __restrict__ v_a,
                 float* __restrict__ out) {
    extern __shared__ char smem[];
    const uint32_t sb = smem_u32(smem);
    const int tid = threadIdx.x;
    const int lane = tid & 31, wid = tid >> 5;
    const int g = lane >> 2, c = lane & 3, l7 = lane & 7;
    const int t8 = (lane >> 3) & 1, t16 = lane >> 4;
    const int wm = wid & 1, wn = wid >> 1;     // 2 x 4 warp grid
    const int mbase = wm * 32, nbase = wn * 32;
    const int b = blockIdx.y, s0 = blockIdx.x * MT;

    float* dec_s = reinterpret_cast<float*>(smem + SM_DEC);
    float* v_s   = reinterpret_cast<float*>(smem + SM_V);
    float* score = reinterpret_cast<float*>(smem + SM_SCORE);
    dec_s[tid]        = g_dec_att[b * ATT + tid];
    dec_s[tid + 256]  = g_dec_att[b * ATT + tid + 256];
    v_s[tid]          = __ldg(v_a + tid);
    v_s[tid + 256]    = __ldg(v_a + tid + 256);
    if (tid < MT) score[tid] = 0.f;

    // ldmatrix row bases
    const int arow = mbase + t8 * 8 + l7;       // A tile: 64 rows
    const int brow = nbase + t16 * 8 + l7;      // B tile: 128 rows
    const int axor = arow & 7;
    const int bxor = brow & 7;

    // A fill coords: 64 rows x 8 16B-chunks = 512 chunks, 2 per thread
    const int q0 = tid, q1 = tid + NTHR;
    const int ar0 = q0 >> 3, ak0 = q0 & 7;
    const int ar1 = q1 >> 3, ak1 = q1 & 7;
    const uint32_t sw0 = (uint32_t)(ar0 * 128 + ((ak0 ^ (ar0 & 7)) << 4));
    const uint32_t sw1 = (uint32_t)(ar1 * 128 + ((ak1 ^ (ar1 & 7)) << 4));

    // B fill coords: 128 rows x 8 chunks = 1024 chunks, 4 per thread
    int brr[4], bkk[4];
    uint32_t swB[4];
#pragma unroll
    for (int j = 0; j < 4; ++j) {
        const int q = tid + j * NTHR;
        brr[j] = q >> 3; bkk[j] = q & 7;
        swB[j] = (uint32_t)(brr[j] * 128 + ((bkk[j] ^ (brr[j] & 7)) << 4));
    }

    const float4* encp0 = reinterpret_cast<const float4*>(
        enc + ((size_t)(s0 + ar0) * BATCH + b) * HID) + ak0 * 2;
    const float4* encp1 = reinterpret_cast<const float4*>(
        enc + ((size_t)(s0 + ar1) * BATCH + b) * HID) + ak1 * 2;

    float4 Araw[4];

    auto ldg_A = [&](int chunk) {
        const int k16 = (chunk & 7) * (KC / 4);   // float4 units
        Araw[0] = __ldg(encp0 + k16);
        Araw[1] = __ldg(encp0 + k16 + 1);
        Araw[2] = __ldg(encp1 + k16);
        Araw[3] = __ldg(encp1 + k16 + 1);
    };
    auto sts_A = [&](int buf) {
        uint4 h;
        h.x = cvt2h(Araw[0].x, Araw[0].y);
        h.y = cvt2h(Araw[0].z, Araw[0].w);
        h.z = cvt2h(Araw[1].x, Araw[1].y);
        h.w = cvt2h(Araw[1].z, Araw[1].w);
        *reinterpret_cast<uint4*>(smem + buf * BUF_B + OFF_A + sw0) = h;
        h.x = cvt2h(Araw[2].x, Araw[2].y);
        h.y = cvt2h(Araw[2].z, Araw[2].w);
        h.z = cvt2h(Araw[3].x, Araw[3].y);
        h.w = cvt2h(Araw[3].z, Araw[3].w);
        *reinterpret_cast<uint4*>(smem + buf * BUF_B + OFF_A + sw1) = h;
    };
    auto cp_B = [&](int chunk, int buf) {
        const int a0 = (chunk >> 3) * AC_N, k0 = (chunk & 7) * KC;
        const uint32_t bb = sb + buf * BUF_B;
#pragma unroll
        for (int j = 0; j < 4; ++j) {
            const size_t gg = (size_t)(a0 + brr[j]) * HID + k0 + bkk[j] * 8;
            cpasync16(bb + OFF_B + swB[j], g_W_h + gg);
        }
        CP_COMMIT();
    };

    // prologue: chunk 0 into buf 0
    ldg_A(0);
    cp_B(0, 0);
    sts_A(0);
    CP_WAIT0();
    __syncthreads();
    ldg_A(1);

    float acc[2][4][4];
#pragma unroll
    for (int mi = 0; mi < 2; ++mi)
#pragma unroll
        for (int nj = 0; nj < 4; ++nj)
#pragma unroll
            for (int e = 0; e < 4; ++e) acc[mi][nj][e] = 0.f;

    for (int it = 0; it < 32; ++it) {
        const int cur = it & 1;

        if (it < 31) {
            sts_A(1 ^ cur);
            cp_B(it + 1, 1 ^ cur);
        }
        if (it < 30) ldg_A(it + 2);

        // ---- mma phase on buf[cur] ----
        const uint32_t bb = sb + cur * BUF_B;
        const uint32_t uA = bb + OFF_A, uB = bb + OFF_B;
#pragma unroll
        for (int ks = 0; ks < 4; ++ks) {
            const int acnk = 2 * ks + t16;
            const int bcnk = 2 * ks + t8;
            uint32_t a0r[4], a1r[4], b0[4], b1[4];

            ldsm4(uB + brow * 128 + ((bcnk ^ bxor) << 4), b0);
            ldsm4(uB + (brow + 16) * 128 + ((bcnk ^ bxor) << 4), b1);
            ldsm4(uA + arow * 128 + ((acnk ^ axor) << 4), a0r);
            ldsm4(uA + (arow + 16) * 128 + ((acnk ^ axor) << 4), a1r);

            MMA(acc[0][0], a0r, b0[0], b0[1]);
            MMA(acc[0][1], a0r, b0[2], b0[3]);
            MMA(acc[0][2], a0r, b1[0], b1[1]);
            MMA(acc[0][3], a0r, b1[2], b1[3]);
            MMA(acc[1][0], a1r, b0[0], b0[1]);
            MMA(acc[1][1], a1r, b0[2], b0[3]);
            MMA(acc[1][2], a1r, b1[0], b1[1]);
            MMA(acc[1][3], a1r, b1[2], b1[3]);
        }

        // end of an a-chunk: tanh + v reduction, reset accumulators
        if ((it & 7) == 7) {
            const int a0 = (it >> 3) * AC_N;
            float pm[4] = {0.f, 0.f, 0.f, 0.f};
#pragma unroll
            for (int mi = 0; mi < 2; ++mi)
#pragma unroll
                for (int nj = 0; nj < 4; ++nj) {
                    const int n = a0 + nbase + nj * 8 + 2 * c;
                    const float dn0 = dec_s[n], dn1 = dec_s[n + 1];
                    const float vn0 = v_s[n],  vn1 = v_s[n + 1];
                    pm[mi * 2 + 0] += vn0 * tanh_fast(acc[mi][nj][0] + dn0)
                                    + vn1 * tanh_fast(acc[mi][nj][1] + dn1);
                    pm[mi * 2 + 1] += vn0 * tanh_fast(acc[mi][nj][2] + dn0)
                                    + vn1 * tanh_fast(acc[mi][nj][3] + dn1);
                }
            atomicAdd(&score[mbase +  0 + g], pm[0]);
            atomicAdd(&score[mbase +  8 + g], pm[1]);
            atomicAdd(&score[mbase + 16 + g], pm[2]);
            atomicAdd(&score[mbase + 24 + g], pm[3]);
#pragma unroll
            for (int mi = 0; mi < 2; ++mi)
#pragma unroll
                for (int nj = 0; nj < 4; ++nj)
#pragma unroll
                    for (int e = 0; e < 4; ++e) acc[mi][nj][e] = 0.f;
        }

        if (it < 31) CP_WAIT0();
        __syncthreads();
    }

    if (tid < MT) out[(size_t)b * S_LEN + s0 + tid] = score[tid];
}

// ---------------- launch ----------------
extern "C" void kernel_launch(void* const* d_in, const int* in_sizes, int n_in,
                              void* d_out, int out_size) {
    const float* dec_out = (const float*)d_in[0];
    const float* enc     = (const float*)d_in[1];
    const float* W_s     = (const float*)d_in[2];
    const float* W_t     = (const float*)d_in[3];
    const float* b_t     = (const float*)d_in[4];
    const float* v_a     = (const float*)d_in[5];
    float* out = (float*)d_out;
    (void)in_sizes; (void)n_in; (void)out_size;

    cudaFuncSetAttribute(score_mma_kernel,
                         cudaFuncAttributeMaxDynamicSharedMemorySize, SM_TOTAL);

    prep_kernel<<<768, 512>>>(W_s, dec_out, W_t, b_t);

    dim3 grid(S_LEN / MT, BATCH);   // (32, 64) = 2048 CTAs
    score_mma_kernel<<<grid, NTHR, SM_TOTAL>>>(enc, v_a, out);
}

// round 12
// speedup vs baseline: 2.2051x; 1.0966x over previous
#include <cuda_runtime.h>
#include <cuda_fp16.h>
#include <cstdint>

// BahdanauScorer: scores[b,s] = sum_a v_a[a] * tanh( enc[s,b,:].W_s[a,:] + dec[b,:].W_t[a,:] + b_t[a] )
// enc (2048,64,512) f32; dec (64,512); W_s,W_t (512,512); b_t,v_a (512); out (64,2048) f32.
//
// fp16 mma.sync. A (enc slab, 64x512) converted ONCE to fp16 smem in the prologue
// (8 swizzled 8KB tiles); steady-state loop streams only B (W_s fp16) via cp.async,
// double buffered. 2 CTAs/SM.

#define S_LEN  2048
#define BATCH  64
#define HID    512
#define ATT    512
#define MT     64       // s-rows per CTA
#define AC_N   128      // a per chunk
#define KC     64       // k per chunk (floats)
#define NTHR   256

// device scratch
__device__ float  g_dec_att[BATCH * ATT];
__device__ __half g_W_h[ATT * HID];

// smem: A 64KB (8 tiles x 8KB, one per kc) + B 2 x 16KB + dec/v/score
#define OFF_A    0
#define OFF_B    65536
#define B_TILE   16384
#define SM_DEC   98304
#define SM_V     100352
#define SM_SCORE 102400
#define SM_TOTAL 102656

__device__ __forceinline__ uint32_t smem_u32(const void* p) {
    uint32_t a;
    asm("{ .reg .u64 t; cvta.to.shared.u64 t, %1; cvt.u32.u64 %0, t; }" : "=r"(a) : "l"(p));
    return a;
}
__device__ __forceinline__ void ldsm4(uint32_t addr, uint32_t* r) {
    asm volatile("ldmatrix.sync.aligned.m8n8.x4.shared.b16 {%0,%1,%2,%3}, [%4];"
                 : "=r"(r[0]), "=r"(r[1]), "=r"(r[2]), "=r"(r[3]) : "r"(addr));
}
__device__ __forceinline__ void cpasync16(uint32_t saddr, const void* gptr) {
    asm volatile("cp.async.cg.shared.global [%0], [%1], 16;" :: "r"(saddr), "l"(gptr) : "memory");
}
#define CP_COMMIT() asm volatile("cp.async.commit_group;" ::: "memory")
#define CP_WAIT0()  asm volatile("cp.async.wait_group 0;" ::: "memory")

#define MMA(d, a, b0, b1)                                                        \
    asm volatile("mma.sync.aligned.m16n8k16.row.col.f32.f16.f16.f32 "            \
                 "{%0,%1,%2,%3},{%4,%5,%6,%7},{%8,%9},{%0,%1,%2,%3};"            \
                 : "+f"((d)[0]), "+f"((d)[1]), "+f"((d)[2]), "+f"((d)[3])        \
                 : "r"((a)[0]), "r"((a)[1]), "r"((a)[2]), "r"((a)[3]),           \
                   "r"(b0), "r"(b1))

__device__ __forceinline__ float tanh_fast(float x) {
    float y;
    asm("tanh.approx.f32 %0, %1;" : "=f"(y) : "f"(x));
    return y;
}
__device__ __forceinline__ uint32_t cvt2h(float x0, float x1) {
    __half2 h = __floats2half2_rn(x0, x1);
    return *reinterpret_cast<uint32_t*>(&h);
}

// ---------------- merged prep kernel ----------------
// blocks 0..511: W_s -> fp16.  blocks 512..767: dec_att (4 blocks per batch).
__global__ void prep_kernel(const float* __restrict__ W_s,
                            const float* __restrict__ dec_out,
                            const float* __restrict__ W_t,
                            const float* __restrict__ b_t) {
    if (blockIdx.x < 512) {
        int i = blockIdx.x * 512 + threadIdx.x;
        g_W_h[i] = __float2half_rn(W_s[i]);
    } else {
        const int bq = blockIdx.x - 512;
        const int b = bq >> 2, aq = bq & 3;
        __shared__ float dsh[HID];
        for (int i = threadIdx.x; i < HID; i += blockDim.x)
            dsh[i] = dec_out[b * HID + i];
        __syncthreads();
        const int a = aq * 128 + (threadIdx.x >> 2);
        const int part = threadIdx.x & 3;
        const float4* w4 = reinterpret_cast<const float4*>(W_t + (size_t)a * HID) + part * 32;
        const float4* d4 = reinterpret_cast<const float4*>(dsh) + part * 32;
        float acc = 0.f;
#pragma unroll 8
        for (int h4 = 0; h4 < 32; ++h4) {
            float4 w = __ldg(&w4[h4]);
            float4 d = d4[h4];
            acc += w.x * d.x + w.y * d.y + w.z * d.z + w.w * d.w;
        }
        acc += __shfl_down_sync(0xffffffffu, acc, 1);
        acc += __shfl_down_sync(0xffffffffu, acc, 2);
        if (part == 0) g_dec_att[b * ATT + a] = acc + b_t[a];
    }
}

// ---------------- main kernel ----------------
extern "C" __global__ void __launch_bounds__(NTHR, 2)
score_mma_kernel(const float* __restrict__ enc,
                 const float* __restrict__ v_a,
                 float* __restrict__ out) {
    extern __shared__ char smem[];
    const uint32_t sb = smem_u32(smem);
    const int tid = threadIdx.x;
    const int lane = tid & 31, wid = tid >> 5;
    const int g = lane >> 2, c = lane & 3, l7 = lane & 7;
    const int t8 = (lane >> 3) & 1, t16 = lane >> 4;
    const int wm = wid & 1, wn = wid >> 1;     // 2 x 4 warp grid
    const int mbase = wm * 32, nbase = wn * 32;
    const int b = blockIdx.y, s0 = blockIdx.x * MT;

    float* dec_s = reinterpret_cast<float*>(smem + SM_DEC);
    float* v_s   = reinterpret_cast<float*>(smem + SM_V);
    float* score = reinterpret_cast<float*>(smem + SM_SCORE);
    dec_s[tid]        = g_dec_att[b * ATT + tid];
    dec_s[tid + 256]  = g_dec_att[b * ATT + tid + 256];
    v_s[tid]          = __ldg(v_a + tid);
    v_s[tid + 256]    = __ldg(v_a + tid + 256);
    if (tid < MT) score[tid] = 0.f;

    // ldmatrix row bases
    const int arow = mbase + t8 * 8 + l7;       // A tile: 64 rows
    const int brow = nbase + t16 * 8 + l7;      // B tile: 128 rows
    const int axor = arow & 7;
    const int bxor = brow & 7;

    // B fill coords: 128 rows x 8 chunks = 1024 chunks, 4 per thread
    int brr[4], bkk[4];
    uint32_t swB[4];
#pragma unroll
    for (int j = 0; j < 4; ++j) {
        const int q = tid + j * NTHR;
        brr[j] = q >> 3; bkk[j] = q & 7;
        swB[j] = (uint32_t)(brr[j] * 128 + ((bkk[j] ^ (brr[j] & 7)) << 4));
    }

    auto cp_B = [&](int chunk, int buf) {
        const int a0 = (chunk >> 3) * AC_N, k0 = (chunk & 7) * KC;
        const uint32_t bb = sb + OFF_B + buf * B_TILE;
#pragma unroll
        for (int j = 0; j < 4; ++j) {
            const size_t gg = (size_t)(a0 + brr[j]) * HID + k0 + bkk[j] * 8;
            cpasync16(bb + swB[j], g_W_h + gg);
        }
        CP_COMMIT();
    };

    // ---- prologue: start B chunk 0, then convert the whole A slab to fp16 smem ----
    cp_B(0, 0);
    // A slab: 64 rows x 512 k fp16 = 4096 16B-chunks; 16 per thread.
#pragma unroll
    for (int j = 0; j < 16; ++j) {
        const int q = tid + j * NTHR;
        const int row = q >> 6, k8 = q & 63;          // k8: 16B chunk within row (8 fp16)
        const float4* src = reinterpret_cast<const float4*>(
            enc + ((size_t)(s0 + row) * BATCH + b) * HID) + k8 * 2;
        const float4 v0 = __ldg(src);
        const float4 v1 = __ldg(src + 1);
        uint4 h;
        h.x = cvt2h(v0.x, v0.y);
        h.y = cvt2h(v0.z, v0.w);
        h.z = cvt2h(v1.x, v1.y);
        h.w = cvt2h(v1.z, v1.w);
        const int kc = k8 >> 3, k16 = k8 & 7;
        const uint32_t off = (uint32_t)(kc * 8192 + row * 128 + ((k16 ^ (row & 7)) << 4));
        *reinterpret_cast<uint4*>(smem + OFF_A + off) = h;
    }
    CP_WAIT0();
    __syncthreads();

    float acc[2][4][4];
#pragma unroll
    for (int mi = 0; mi < 2; ++mi)
#pragma unroll
        for (int nj = 0; nj < 4; ++nj)
#pragma unroll
            for (int e = 0; e < 4; ++e) acc[mi][nj][e] = 0.f;

    for (int it = 0; it < 32; ++it) {
        const int cur = it & 1;

        if (it < 31) cp_B(it + 1, 1 ^ cur);

        // ---- mma phase: A tile for kc = it&7 (persistent), B in buf[cur] ----
        const uint32_t uA = sb + OFF_A + (it & 7) * 8192;
        const uint32_t uB = sb + OFF_B + cur * B_TILE;
#pragma unroll
        for (int ks = 0; ks < 4; ++ks) {
            const int acnk = 2 * ks + t16;
            const int bcnk = 2 * ks + t8;
            uint32_t a0r[4], a1r[4], b0[4], b1[4];

            ldsm4(uB + brow * 128 + ((bcnk ^ bxor) << 4), b0);
            ldsm4(uB + (brow + 16) * 128 + ((bcnk ^ bxor) << 4), b1);
            ldsm4(uA + arow * 128 + ((acnk ^ axor) << 4), a0r);
            ldsm4(uA + (arow + 16) * 128 + ((acnk ^ axor) << 4), a1r);

            MMA(acc[0][0], a0r, b0[0], b0[1]);
            MMA(acc[0][1], a0r, b0[2], b0[3]);
            MMA(acc[0][2], a0r, b1[0], b1[1]);
            MMA(acc[0][3], a0r, b1[2], b1[3]);
            MMA(acc[1][0], a1r, b0[0], b0[1]);
            MMA(acc[1][1], a1r, b0[2], b0[3]);
            MMA(acc[1][2], a1r, b1[0], b1[1]);
            MMA(acc[1][3], a1r, b1[2], b1[3]);
        }

        // end of an a-chunk: tanh + v reduction, reset accumulators
        if ((it & 7) == 7) {
            const int a0 = (it >> 3) * AC_N;
            float pm[4] = {0.f, 0.f, 0.f, 0.f};
#pragma unroll
            for (int mi = 0; mi < 2; ++mi)
#pragma unroll
                for (int nj = 0; nj < 4; ++nj) {
                    const int n = a0 + nbase + nj * 8 + 2 * c;
                    const float dn0 = dec_s[n], dn1 = dec_s[n + 1];
                    const float vn0 = v_s[n],  vn1 = v_s[n + 1];
                    pm[mi * 2 + 0] += vn0 * tanh_fast(acc[mi][nj][0] + dn0)
                                    + vn1 * tanh_fast(acc[mi][nj][1] + dn1);
                    pm[mi * 2 + 1] += vn0 * tanh_fast(acc[mi][nj][2] + dn0)
                                    + vn1 * tanh_fast(acc[mi][nj][3] + dn1);
                }
            atomicAdd(&score[mbase +  0 + g], pm[0]);
            atomicAdd(&score[mbase +  8 + g], pm[1]);
            atomicAdd(&score[mbase + 16 + g], pm[2]);
            atomicAdd(&score[mbase + 24 + g], pm[3]);
#pragma unroll
            for (int mi = 0; mi < 2; ++mi)
#pragma unroll
                for (int nj = 0; nj < 4; ++nj)
#pragma unroll
                    for (int e = 0; e < 4; ++e) acc[mi][nj][e] = 0.f;
        }

        if (it < 31) CP_WAIT0();
        __syncthreads();
    }

    if (tid < MT) out[(size_t)b * S_LEN + s0 + tid] = score[tid];
}

// ---------------- launch ----------------
extern "C" void kernel_launch(void* const* d_in, const int* in_sizes, int n_in,
                              void* d_out, int out_size) {
    const float* dec_out = (const float*)d_in[0];
    const float* enc     = (const float*)d_in[1];
    const float* W_s     = (const float*)d_in[2];
    const float* W_t     = (const float*)d_in[3];
    const float* b_t     = (const float*)d_in[4];
    const float* v_a     = (const float*)d_in[5];
    float* out = (float*)d_out;
    (void)in_sizes; (void)n_in; (void)out_size;

    cudaFuncSetAttribute(score_mma_kernel,
                         cudaFuncAttributeMaxDynamicSharedMemorySize, SM_TOTAL);

    prep_kernel<<<768, 512>>>(W_s, dec_out, W_t, b_t);

    dim3 grid(S_LEN / MT, BATCH);   // (32, 64) = 2048 CTAs
    score_mma_kernel<<<grid, NTHR, SM_TOTAL>>>(enc, v_a, out);
}